// round 1
// baseline (speedup 1.0000x reference)
#include <cuda_runtime.h>
#include <cstdint>

#define GRID_D 128
#define NUM_CELLS (128*128*128)
#define INV_CELL 64.0f

// One thread per particle. Each particle scatters {m*w, m*w*v} to the 8
// corners of its enclosing cell with a single red.global.add.v4.f32 per
// corner (output layout [C,4] = {mass, mom.x, mom.y, mom.z} is a contiguous
// 16B-aligned float4 per cell).
__global__ __launch_bounds__(256) void p2g_kernel(
    const float* __restrict__ pos,
    const float* __restrict__ vel,
    const float* __restrict__ mass,
    float* __restrict__ out,
    int n)
{
    int i = blockIdx.x * blockDim.x + threadIdx.x;
    if (i >= n) return;

    // position in cell units
    float rx = pos[3 * i + 0] * INV_CELL;
    float ry = pos[3 * i + 1] * INV_CELL;
    float rz = pos[3 * i + 2] * INV_CELL;

    float bx = floorf(rx), by = floorf(ry), bz = floorf(rz);
    int ix = (int)bx, iy = (int)by, iz = (int)bz;

    // fractional offsets in [0,1): corner-0 weight = 1-f, corner-1 weight = f
    float fx = rx - bx, fy = ry - by, fz = rz - bz;
    float wx[2] = {1.0f - fx, fx};
    float wy[2] = {1.0f - fy, fy};
    float wz[2] = {1.0f - fz, fz};

    float m  = mass[i];
    float vx = vel[3 * i + 0];
    float vy = vel[3 * i + 1];
    float vz = vel[3 * i + 2];

    // hash = z + x*GRID_D + y*GRID_D*GRID_D
    int base_hash = iz + ix * GRID_D + iy * (GRID_D * GRID_D);

#pragma unroll
    for (int di = 0; di < 2; di++) {
#pragma unroll
        for (int dj = 0; dj < 2; dj++) {
#pragma unroll
            for (int dk = 0; dk < 2; dk++) {
                float w = wx[di] * wy[dj] * wz[dk] * m;
                int h = base_hash + dk + di * GRID_D + dj * (GRID_D * GRID_D);
                if ((unsigned)h < (unsigned)NUM_CELLS) {
                    float* p = out + 4ull * (unsigned)h;
                    float a0 = w;
                    float a1 = w * vx;
                    float a2 = w * vy;
                    float a3 = w * vz;
                    asm volatile(
                        "red.global.add.v4.f32 [%0], {%1, %2, %3, %4};"
                        :: "l"(p), "f"(a0), "f"(a1), "f"(a2), "f"(a3)
                        : "memory");
                }
            }
        }
    }
}

extern "C" void kernel_launch(void* const* d_in, const int* in_sizes, int n_in,
                              void* d_out, int out_size)
{
    const float* pos  = (const float*)d_in[0];
    const float* vel  = (const float*)d_in[1];
    const float* mass = (const float*)d_in[2];
    float* out = (float*)d_out;
    int n = in_sizes[2];  // mass_stack element count == NUM_POINTS

    cudaMemsetAsync(d_out, 0, (size_t)out_size * sizeof(float));

    int threads = 256;
    int blocks = (n + threads - 1) / threads;
    p2g_kernel<<<blocks, threads>>>(pos, vel, mass, out, n);
}